// round 14
// baseline (speedup 1.0000x reference)
#include <cuda_runtime.h>
#include <cstdint>

namespace {

constexpr unsigned FULL = 0xffffffffu;

// ---------------------------------------------------------------------------
// Barrier-free final variant (math validated rounds 4-13).
//
// X basis: RX -> RZ, CNOT ring -> GF(2)-linear map P.
//   <Z7> = (1/256) sum_v cos( sum_{active g} theta_g * (-1)^{par(a_g & v)} )
// Embed gates collapse to qubits {0,4} (P^{-4} e7 = 0x11) =>
//   out_c = A_c cos(x0+x4) - B_c sin(x0+x4) + D_c cos(x0-x4) - E_c sin(x0-x4)
// Here each WARP owns one channel and 32 pixels: lanes cover the low 5 bits
// of v, a Walsh split over the high 3 bits (groups T0..T7 by mask bits 5-7)
// yields all 8 cosets from one gate pass, and a shfl butterfly leaves the
// full (A,B,D,E) in every lane. No shared memory, no __syncthreads.
// ---------------------------------------------------------------------------

struct M8 { uint8_t r[8]; };

__host__ __device__ constexpr M8 makeP() {
    M8 P{};
    for (int q = 0; q < 7; ++q) P.r[q] = uint8_t((1u << q) | (1u << (q + 1)));
    P.r[7] = uint8_t((1u << 7) | 3u);
    return P;
}
__host__ __device__ constexpr M8 ident() {
    M8 I{};
    for (int q = 0; q < 8; ++q) I.r[q] = uint8_t(1u << q);
    return I;
}
__host__ __device__ constexpr M8 matmul(const M8& A, const M8& B) {
    M8 C{};
    for (int q = 0; q < 8; ++q) {
        uint8_t row = 0;
        for (int k = 0; k < 8; ++k)
            if ((A.r[q] >> k) & 1u) row ^= B.r[k];
        C.r[q] = row;
    }
    return C;
}
__host__ __device__ constexpr M8 inverse(const M8& A) {
    unsigned m[8] = {};
    for (int q = 0; q < 8; ++q) m[q] = (unsigned)A.r[q] | (1u << (8 + q));
    for (int col = 0; col < 8; ++col) {
        int piv = col;
        while (!((m[piv] >> col) & 1u)) ++piv;
        unsigned t = m[col]; m[col] = m[piv]; m[piv] = t;
        for (int r = 0; r < 8; ++r)
            if (r != col && ((m[r] >> col) & 1u)) m[r] ^= m[col];
    }
    M8 R{};
    for (int q = 0; q < 8; ++q) R.r[q] = uint8_t(m[q] >> 8);
    return R;
}
__host__ __device__ constexpr M8 Pinv_pow(int k) {
    M8 Pi = inverse(makeP());
    M8 R = ident();
    for (int i = 0; i < k; ++i) R = matmul(Pi, R);
    return R;
}

struct WGates { int n; uint8_t a[32]; uint8_t idx[32]; };
__host__ __device__ constexpr WGates makeWG() {
    WGates G{};
    for (int l = 0; l < 4; ++l) {
        M8 A = Pinv_pow(4 - l);
        for (int q = 0; q < 8; ++q)
            if ((A.r[q] >> 7) & 1u) {
                G.a[G.n] = A.r[q];
                G.idx[G.n] = uint8_t(l * 8 + q);
                ++G.n;
            }
    }
    return G;
}
struct XGates { int n; uint8_t a[8]; uint8_t q[8]; };
__host__ __device__ constexpr XGates makeXG() {
    XGates G{};
    M8 A = Pinv_pow(4);
    for (int q = 0; q < 8; ++q)
        if ((A.r[q] >> 7) & 1u) {
            G.a[G.n] = A.r[q];
            G.q[G.n] = uint8_t(q);
            ++G.n;
        }
    return G;
}

// Sign-word columns over the LOW 5 bits of v: bit g of COL[i] = bit i of a_g.
struct Cols5 { uint32_t c[5]; };
__host__ __device__ constexpr Cols5 makeCols5() {
    Cols5 C{};
    WGates G = makeWG();
    for (int i = 0; i < 5; ++i)
        for (int g = 0; g < G.n; ++g)
            if ((G.a[g] >> i) & 1u) C.c[i] |= 1u << g;
    return C;
}

__device__ __forceinline__ void cw_sincos(float S, float& sv, float& cv) {
    const float k = rintf(S * 0.15915494309189535f);
    float r = fmaf(k, -6.283185482025146484f, S);
    r = fmaf(k, 1.7484556000744885e-7f, r);
    __sincosf(r, &sv, &cv);
}

constexpr int kThreads = 256;                 // 8 warps/block
constexpr int kBlocks = 128;                  // 1024 warps = 4 ch x 256 groups

__global__ __launch_bounds__(kThreads)
void qconv_warp(const float* __restrict__ x, const float* __restrict__ w,
                float* __restrict__ out) {
    constexpr WGates WG = makeWG();
    constexpr XGates XG = makeXG();
    constexpr Cols5 CL = makeCols5();
    static_assert(XG.n == 2, "embed collapse assumption violated");
    constexpr int MA = XG.a[0];
    constexpr int MB = XG.a[1];

    const int tid = threadIdx.x;
    const int lane = tid & 31;
    const int g = blockIdx.x * 8 + (tid >> 5);   // global warp id, 0..1023

    const int oc = g & 3;                        // channel for this warp
    const int pixel = (g >> 2) * 32 + lane;      // 32 pixels per warp
    const int b = pixel >> 12;
    const int i = (pixel >> 6) & 63;
    const int j = pixel & 63;

    // Prefetch this lane's pixel inputs (overlaps with the coset math).
    constexpr int q0 = XG.q[0], q1 = XG.q[1];
    constexpr int c0 = q0 >> 2, d0i = (q0 >> 1) & 1, d0j = q0 & 1;
    constexpr int c1 = q1 >> 2, d1i = (q1 >> 1) & 1, d1j = q1 & 1;
    const float x0 =
        __ldg(&x[((b * 2 + c0) * 128 + (2 * i + d0i)) * 128 + (2 * j + d0j)]);
    const float x1 =
        __ldg(&x[((b * 2 + c1) * 128 + (2 * i + d1i)) * 128 + (2 * j + d1j)]);
    const int out_idx = ((b * 4 + oc) * 64 + i) * 64 + j;

    // ---- Coset sums: lane = low 5 bits of v; high 3 bits via Walsh. ----
    uint32_t sw = 0;
#pragma unroll
    for (int ii = 0; ii < 5; ++ii)
        if ((lane >> ii) & 1) sw ^= CL.c[ii];

    float T[8] = {0.f, 0.f, 0.f, 0.f, 0.f, 0.f, 0.f, 0.f};
#pragma unroll
    for (int gg = 0; gg < WG.n; ++gg) {
        const float th = __ldg(&w[oc * 32 + (int)WG.idx[gg]]);
        const float sth =
            __int_as_float(__float_as_int(th) ^ (((sw >> gg) & 1u) << 31));
        constexpr int dummy = 0; (void)dummy;
        const int grp = ((int)WG.a[gg] >> 5) & 7;   // compile-time constant
        T[grp] += sth;
    }

    // Low-bit parities of the measurement masks (lane part).
    const int pA_lo = __popc(MA & 31 & lane) & 1;
    const int pB_lo = __popc(MB & 31 & lane) & 1;

    float A = 0.f, B = 0.f, D = 0.f, E = 0.f;
#pragma unroll
    for (int k = 0; k < 8; ++k) {
        float S = 0.f;
#pragma unroll
        for (int jj = 0; jj < 8; ++jj)
            S += (__popc(jj & k) & 1) ? -T[jj] : T[jj];   // signs constexpr
        float sv, cv;
        cw_sincos(S, sv, cv);
        const int pA = pA_lo ^ (__popc((MA >> 5) & k) & 1);
        const int pB = pB_lo ^ (__popc((MB >> 5) & k) & 1);
        const float sg = pA ? -sv : sv;
        if (pA == pB) { A += cv; B += sg; }
        else          { D += cv; E += sg; }
    }

    // Full butterfly: every lane ends with the complete channel sums.
#pragma unroll
    for (int off = 16; off > 0; off >>= 1) {
        A += __shfl_xor_sync(FULL, A, off);
        B += __shfl_xor_sync(FULL, B, off);
        D += __shfl_xor_sync(FULL, D, off);
        E += __shfl_xor_sync(FULL, E, off);
    }

    // ---- Pixel evaluation (no barrier was needed anywhere). ----
    float sp, cp, sm, cm;
    cw_sincos(x0 + x1, sp, cp);
    cw_sincos(x0 - x1, sm, cm);

    out[out_idx] =
        fmaf(A, cp, fmaf(-B, sp, fmaf(D, cm, -E * sm))) * (1.f / 256.f);
}

}  // namespace

extern "C" void kernel_launch(void* const* d_in, const int* /*in_sizes*/, int /*n_in*/,
                              void* d_out, int /*out_size*/) {
    const float* x = (const float*)d_in[0];
    const float* w = (const float*)d_in[1];
    float* out = (float*)d_out;
    qconv_warp<<<kBlocks, kThreads>>>(x, w, out);
}

// round 15
// speedup vs baseline: 1.0769x; 1.0769x over previous
#include <cuda_runtime.h>
#include <cstdint>

namespace {

constexpr unsigned FULL = 0xffffffffu;

// ---------------------------------------------------------------------------
// FINAL — committed kernel (structure validated and re-benched rounds 10-13).
//
// Math: conjugate the whole circuit by H^⊗8. RX -> RZ (diagonal), each CNOT
// ring -> GF(2)-linear basis map P. The state stays a uniform-magnitude pure
// phase, and
//   <Z7> = (1/256) sum_v cos( sum_{active g} theta_g * (-1)^{par(a_g & v)} ),
// where gate g (weight or embed angle) is active iff bit7 of row q of P^{-k}
// is set (k = rings remaining after g), with sign mask a_g = that row.
// The embed gates collapse to qubits {0,4} (P^{-4} e7 = 0x11), so the
// data-dependent phase is +-x0 +- x4 and the sum factors:
//   out_c = A_c cos(x0+x4) - B_c sin(x0+x4) + D_c cos(x0-x4) - E_c sin(x0-x4)
// with (A,B,D,E)_c weight-only coset sums computed once per block (phase 1)
// and applied per pixel (phase 2). Single launch, single barrier.
// ---------------------------------------------------------------------------

struct M8 { uint8_t r[8]; };

__host__ __device__ constexpr M8 makeP() {
    M8 P{};
    for (int q = 0; q < 7; ++q) P.r[q] = uint8_t((1u << q) | (1u << (q + 1)));
    P.r[7] = uint8_t((1u << 7) | 3u);
    return P;
}
__host__ __device__ constexpr M8 ident() {
    M8 I{};
    for (int q = 0; q < 8; ++q) I.r[q] = uint8_t(1u << q);
    return I;
}
__host__ __device__ constexpr M8 matmul(const M8& A, const M8& B) {
    M8 C{};
    for (int q = 0; q < 8; ++q) {
        uint8_t row = 0;
        for (int k = 0; k < 8; ++k)
            if ((A.r[q] >> k) & 1u) row ^= B.r[k];
        C.r[q] = row;
    }
    return C;
}
__host__ __device__ constexpr M8 inverse(const M8& A) {
    unsigned m[8] = {};
    for (int q = 0; q < 8; ++q) m[q] = (unsigned)A.r[q] | (1u << (8 + q));
    for (int col = 0; col < 8; ++col) {
        int piv = col;
        while (!((m[piv] >> col) & 1u)) ++piv;
        unsigned t = m[col]; m[col] = m[piv]; m[piv] = t;
        for (int r = 0; r < 8; ++r)
            if (r != col && ((m[r] >> col) & 1u)) m[r] ^= m[col];
    }
    M8 R{};
    for (int q = 0; q < 8; ++q) R.r[q] = uint8_t(m[q] >> 8);
    return R;
}
__host__ __device__ constexpr M8 Pinv_pow(int k) {
    M8 Pi = inverse(makeP());
    M8 R = ident();
    for (int i = 0; i < k; ++i) R = matmul(Pi, R);
    return R;
}

struct WGates { int n; uint8_t a[32]; uint8_t idx[32]; };
__host__ __device__ constexpr WGates makeWG() {
    WGates G{};
    for (int l = 0; l < 4; ++l) {
        M8 A = Pinv_pow(4 - l);
        for (int q = 0; q < 8; ++q)
            if ((A.r[q] >> 7) & 1u) {
                G.a[G.n] = A.r[q];
                G.idx[G.n] = uint8_t(l * 8 + q);
                ++G.n;
            }
    }
    return G;
}
struct XGates { int n; uint8_t a[8]; uint8_t q[8]; };
__host__ __device__ constexpr XGates makeXG() {
    XGates G{};
    M8 A = Pinv_pow(4);
    for (int q = 0; q < 8; ++q)
        if ((A.r[q] >> 7) & 1u) {
            G.a[G.n] = A.r[q];
            G.q[G.n] = uint8_t(q);
            ++G.n;
        }
    return G;
}

// Sign-word columns over the LOW 6 bits of v: bit g of COL[i] = bit i of a_g.
struct Cols { uint32_t c[6]; };
__host__ __device__ constexpr Cols makeCols() {
    Cols C{};
    WGates G = makeWG();
    for (int i = 0; i < 6; ++i)
        for (int g = 0; g < G.n; ++g)
            if ((G.a[g] >> i) & 1u) C.c[i] |= 1u << g;
    return C;
}

__device__ __forceinline__ void cw_sincos(float S, float& sv, float& cv) {
    // Cody-Waite reduction to [-pi, pi], then MUFU sincos.
    const float k = rintf(S * 0.15915494309189535f);
    float r = fmaf(k, -6.283185482025146484f, S);
    r = fmaf(k, 1.7484556000744885e-7f, r);
    __sincosf(r, &sv, &cv);
}

constexpr int kThreads = 256;
constexpr int kPixPerBlock = 64;
constexpr int kBlocks = 8192 / kPixPerBlock;   // 128 blocks, one wave

__global__ __launch_bounds__(kThreads)
void qconv_fused(const float* __restrict__ x, const float* __restrict__ w,
                 float* __restrict__ out) {
    constexpr WGates WG = makeWG();
    constexpr XGates XG = makeXG();
    constexpr Cols CL = makeCols();
    static_assert(XG.n == 2, "embed collapse assumption violated");
    constexpr int MA = XG.a[0];
    constexpr int MB = XG.a[1];

    __shared__ float4 s_part[8];   // per warp: {A, B, D, E} pre-scaled 1/256

    const int tid = threadIdx.x;
    const int lane = tid & 31;
    const int wid = tid >> 5;

    // Every thread owns one (oc, pix) output; x loads broadcast 4-way.
    const int pix = tid & 63;
    const int oc = tid >> 6;
    const int pixel = blockIdx.x * kPixPerBlock + pix;
    const int b = pixel >> 12;
    const int i = (pixel >> 6) & 63;
    const int j = pixel & 63;
    constexpr int q0 = XG.q[0], q1 = XG.q[1];
    constexpr int c0 = q0 >> 2, d0i = (q0 >> 1) & 1, d0j = q0 & 1;
    constexpr int c1 = q1 >> 2, d1i = (q1 >> 1) & 1, d1j = q1 & 1;
    const float x0 =
        __ldg(&x[((b * 2 + c0) * 128 + (2 * i + d0i)) * 128 + (2 * j + d0j)]);
    const float x1 =
        __ldg(&x[((b * 2 + c1) * 128 + (2 * i + d1i)) * 128 + (2 * j + d1j)]);
    const int out_idx = ((b * 4 + oc) * 64 + i) * 64 + j;

    // ---- Phase 1: channel c = oc, low bits vt = pix; high 2 bits of v via
    // Walsh split. Weights read directly (broadcast LDG). ----
    const int vt = pix;

    uint32_t sw = 0;
#pragma unroll
    for (int ii = 0; ii < 6; ++ii)
        if ((vt >> ii) & 1) sw ^= CL.c[ii];

    float T0 = 0.f, T1 = 0.f, T2 = 0.f, T3 = 0.f;
#pragma unroll
    for (int g = 0; g < WG.n; ++g) {
        const float th = __ldg(&w[oc * 32 + (int)WG.idx[g]]);
        const float sth =
            __int_as_float(__float_as_int(th) ^ (((sw >> g) & 1u) << 31));
        const int grp = ((int)WG.a[g] >> 6) & 3;   // compile-time constant
        if (grp == 0) T0 += sth;
        else if (grp == 1) T1 += sth;
        else if (grp == 2) T2 += sth;
        else T3 += sth;
    }

    float A = 0.f, B = 0.f, D = 0.f, E = 0.f;
#pragma unroll
    for (int k = 0; k < 4; ++k) {
        const float f1 = (k & 1) ? -T1 : T1;
        const float f2 = (k & 2) ? -T2 : T2;
        const float f3 = (((k ^ (k >> 1)) & 1)) ? -T3 : T3;
        const float S = T0 + f1 + f2 + f3;
        float sv, cv;
        cw_sincos(S, sv, cv);
        const int v = vt | (k << 6);
        const int pA = __popc(MA & v) & 1;
        const int pB = __popc(MB & v) & 1;
        const float sg = pA ? -sv : sv;
        if (pA == pB) { A += cv; B += sg; }
        else          { D += cv; E += sg; }
    }

#pragma unroll
    for (int off = 16; off > 0; off >>= 1) {
        A += __shfl_xor_sync(FULL, A, off);
        B += __shfl_xor_sync(FULL, B, off);
        D += __shfl_xor_sync(FULL, D, off);
        E += __shfl_xor_sync(FULL, E, off);
    }
    // 1/256 folded here (off the post-barrier critical tail).
    if (lane == 0)
        s_part[wid] = make_float4(A * (1.f / 256.f), B * (1.f / 256.f),
                                  D * (1.f / 256.f), E * (1.f / 256.f));
    __syncthreads();   // single barrier

    // ---- Phase 2: one output per thread; sincos AFTER the barrier (R11
    // showed hoisting lengthens the pre-barrier path and regresses). ----
    const float4 p0 = s_part[2 * oc];
    const float4 p1 = s_part[2 * oc + 1];
    const float tA = p0.x + p1.x;
    const float tB = p0.y + p1.y;
    const float tD = p0.z + p1.z;
    const float tE = p0.w + p1.w;

    float sp, cp, sm, cm;
    cw_sincos(x0 + x1, sp, cp);
    cw_sincos(x0 - x1, sm, cm);

    out[out_idx] = fmaf(tA, cp, fmaf(-tB, sp, fmaf(tD, cm, -tE * sm)));
}

}  // namespace

extern "C" void kernel_launch(void* const* d_in, const int* /*in_sizes*/, int /*n_in*/,
                              void* d_out, int /*out_size*/) {
    const float* x = (const float*)d_in[0];
    const float* w = (const float*)d_in[1];
    float* out = (float*)d_out;
    qconv_fused<<<kBlocks, kThreads>>>(x, w, out);
}